// round 1
// baseline (speedup 1.0000x reference)
#include <cuda_runtime.h>
#include <cuda_bf16.h>

#define B_  256
#define T_  512
#define I_  512
#define H_  1024
#define NB_ 4
#define HB_ 256
#define O_  128
#define M_  (B_ * T_)   // 131072

// Scratch: u[t][b][h] (drive currents for every timestep), and acc[b][h]
__device__ float g_u[(size_t)T_ * B_ * H_];   // 512 MB
__device__ float g_acc[B_ * H_];

// ---------------------------------------------------------------------------
// Phase 1: u[(t,b), h] = x[b,t,:] @ Wcat[:, h]
//   Wcat[i, nb*HB+hb] = W_branch[nb, i, hb]
// fp32 SGEMM, 128x128 tile, 8x8 per thread, K-chunks of 16.
// ---------------------------------------------------------------------------
#define BM 128
#define BN 128
#define BK 16

__global__ __launch_bounds__(256, 2)
void gemm_xw_kernel(const float* __restrict__ X, const float* __restrict__ Wb) {
    __shared__ float As[BK][BM];
    __shared__ float Bs[BK][BN];

    const int tid = threadIdx.x;
    const int n0  = blockIdx.x * BN;   // over H (8 tiles) -> fastest grid dim (A reuse in L2)
    const int m0  = blockIdx.y * BM;   // over B*T (1024 tiles)

    // n-tile lives inside one branch (BN=128 <= HB=256, aligned)
    const int nb  = n0 / HB_;
    const int hb0 = n0 % HB_;
    const float* Wbase = Wb + (size_t)nb * I_ * HB_ + hb0;

    const int tx = tid % 16;   // n direction
    const int ty = tid / 16;   // m direction

    float acc[8][8];
#pragma unroll
    for (int i = 0; i < 8; i++)
#pragma unroll
        for (int j = 0; j < 8; j++) acc[i][j] = 0.f;

    // A-tile load mapping: 128x16 floats = 512 float4, 2 per thread
    const int a_row = tid / 4;   // 0..63
    const int a_c4  = tid % 4;   // 0..3
    // B-tile load mapping: 16x128 floats = 512 float4, 2 per thread
    const int b_k   = tid / 32;  // 0..7
    const int b_c4  = tid % 32;  // 0..31

    for (int k0 = 0; k0 < I_; k0 += BK) {
#pragma unroll
        for (int r = 0; r < 2; r++) {
            int row = a_row + r * 64;
            float4 v = *reinterpret_cast<const float4*>(
                X + (size_t)(m0 + row) * I_ + k0 + a_c4 * 4);
            As[a_c4 * 4 + 0][row] = v.x;
            As[a_c4 * 4 + 1][row] = v.y;
            As[a_c4 * 4 + 2][row] = v.z;
            As[a_c4 * 4 + 3][row] = v.w;
        }
#pragma unroll
        for (int r = 0; r < 2; r++) {
            int k = b_k + r * 8;
            float4 v = *reinterpret_cast<const float4*>(
                Wbase + (size_t)(k0 + k) * HB_ + b_c4 * 4);
            *reinterpret_cast<float4*>(&Bs[k][b_c4 * 4]) = v;
        }
        __syncthreads();

#pragma unroll
        for (int kk = 0; kk < BK; kk++) {
            float a[8], bb[8];
#pragma unroll
            for (int i = 0; i < 8; i++) a[i]  = As[kk][ty * 8 + i];
#pragma unroll
            for (int j = 0; j < 8; j++) bb[j] = Bs[kk][tx * 8 + j];
#pragma unroll
            for (int i = 0; i < 8; i++)
#pragma unroll
                for (int j = 0; j < 8; j++)
                    acc[i][j] = fmaf(a[i], bb[j], acc[i][j]);
        }
        __syncthreads();
    }

    // Write out to u[t][b][h]; row m = b*T + t (x is (B,T,I) contiguous)
#pragma unroll
    for (int i = 0; i < 8; i++) {
        int m = m0 + ty * 8 + i;
        int b = m >> 9;          // / T_
        int t = m & (T_ - 1);
        float* dst = g_u + ((size_t)t * B_ + b) * H_ + n0 + tx * 8;
        *reinterpret_cast<float4*>(dst) =
            make_float4(acc[i][0], acc[i][1], acc[i][2], acc[i][3]);
        *reinterpret_cast<float4*>(dst + 4) =
            make_float4(acc[i][4], acc[i][5], acc[i][6], acc[i][7]);
    }
}

// ---------------------------------------------------------------------------
// Phase 2: per-neuron LIF recurrence over T. One thread per (b,h).
//   d = beta*d + (1-beta)*u ; v = alpha*v + (1-alpha)*d - s_prev
//   s = (v > 1) ; acc += s for t >= T/2
// Coalesced reads of u (stride B*H across t).
// ---------------------------------------------------------------------------
__global__ __launch_bounds__(256)
void recur_kernel(const float* __restrict__ v0,
                  const float* __restrict__ tau_n,
                  const float* __restrict__ tau_m) {
    const int idx = blockIdx.x * blockDim.x + threadIdx.x;  // b*H + h
    const int h   = idx & (H_ - 1);

    // tau_n is (NB,HB) contiguous -> flat index nb*HB+hb == h
    const float beta  = 1.f / (1.f + expf(-tau_n[h]));
    const float alpha = 1.f / (1.f + expf(-tau_m[h]));
    const float omb = 1.f - beta;
    const float oma = 1.f - alpha;

    float d = 0.f, v = v0[idx], s = 0.f, acc = 0.f;
    const float* up = g_u + idx;
    const size_t stride = (size_t)B_ * H_;

#pragma unroll 4
    for (int t = 0; t < T_; t++) {
        float u = up[(size_t)t * stride];
        d = beta * d + omb * u;
        v = alpha * v + oma * d - s;   // s holds V_TH * s_prev (V_TH = 1)
        s = (v > 1.0f) ? 1.0f : 0.0f;  // sign(v - V_TH > 0), identical predicate
        if (t >= T_ / 2) acc += s;
    }
    g_acc[idx] = acc;
}

// ---------------------------------------------------------------------------
// Phase 3: out[b, o] = acc[b, :] @ W_out[:, o] + b_out[o]
// One block per batch row, one thread per output column.
// ---------------------------------------------------------------------------
__global__ __launch_bounds__(O_)
void out_kernel(const float* __restrict__ Wout,
                const float* __restrict__ bout,
                float* __restrict__ out) {
    __shared__ float sacc[H_];
    const int b = blockIdx.x;
    const int o = threadIdx.x;

    for (int h = o; h < H_; h += O_) sacc[h] = g_acc[b * H_ + h];
    __syncthreads();

    float sum = bout[o];
#pragma unroll 8
    for (int h = 0; h < H_; h++)
        sum = fmaf(sacc[h], Wout[h * O_ + o], sum);
    out[b * O_ + o] = sum;
}

// ---------------------------------------------------------------------------
extern "C" void kernel_launch(void* const* d_in, const int* in_sizes, int n_in,
                              void* d_out, int out_size) {
    const float* x     = (const float*)d_in[0];  // (B,T,I)
    const float* v0    = (const float*)d_in[1];  // (B,H)
    const float* Wb    = (const float*)d_in[2];  // (NB,I,HB)
    const float* tau_n = (const float*)d_in[3];  // (NB,HB)
    const float* tau_m = (const float*)d_in[4];  // (H,)
    const float* Wout  = (const float*)d_in[5];  // (H,O)
    const float* bout  = (const float*)d_in[6];  // (O,)
    float* out = (float*)d_out;                  // (B,O)

    (void)in_sizes; (void)n_in; (void)out_size;

    dim3 ggrid(H_ / BN, M_ / BM);                // (8, 1024)
    gemm_xw_kernel<<<ggrid, 256>>>(x, Wb);
    recur_kernel<<<(B_ * H_) / 256, 256>>>(v0, tau_n, tau_m);
    out_kernel<<<B_, O_>>>(Wout, bout, out);
}

// round 7
// speedup vs baseline: 1.3708x; 1.3708x over previous
#include <cuda_runtime.h>
#include <cuda_bf16.h>
#include <cstdint>
#include <cstddef>

#define B_  256
#define T_  512
#define I_  512
#define H_  1024
#define HB_ 256
#define O_  128
#define M_  (B_ * T_)     // 131072

// ---------------------------------------------------------------------------
// Scratch (device globals; allocation is forbidden)
// ---------------------------------------------------------------------------
__device__ __align__(1024) float g_u[(size_t)T_ * B_ * H_];       // 512 MB
__device__ __align__(1024) float g_acc[B_ * H_];
__device__ __align__(1024) __nv_bfloat16 g_xh[(size_t)M_ * I_];   // 128 MB each
__device__ __align__(1024) __nv_bfloat16 g_xm[(size_t)M_ * I_];
__device__ __align__(1024) __nv_bfloat16 g_xl[(size_t)M_ * I_];
__device__ __align__(1024) __nv_bfloat16 g_wh[H_ * I_];           // 1 MB each, [n][k]
__device__ __align__(1024) __nv_bfloat16 g_wm[H_ * I_];
__device__ __align__(1024) __nv_bfloat16 g_wl[H_ * I_];

// ---------------------------------------------------------------------------
// Split kernels: x (and W) -> bf16 high/mid/low parts
// ---------------------------------------------------------------------------
__global__ __launch_bounds__(256)
void split_x_kernel(const float* __restrict__ x) {
    size_t i = (size_t)blockIdx.x * blockDim.x + threadIdx.x;  // float4 index
    float4 v = reinterpret_cast<const float4*>(x)[i];
    float f[4] = {v.x, v.y, v.z, v.w};
    __nv_bfloat16 h[4], m4[4], l[4];
#pragma unroll
    for (int j = 0; j < 4; j++) {
        float a = f[j];
        __nv_bfloat16 hh = __float2bfloat16_rn(a);
        float r = a - __bfloat162float(hh);
        __nv_bfloat16 mm = __float2bfloat16_rn(r);
        float r2 = r - __bfloat162float(mm);
        h[j] = hh; m4[j] = mm; l[j] = __float2bfloat16_rn(r2);
    }
    __nv_bfloat162* ph = reinterpret_cast<__nv_bfloat162*>(g_xh);
    __nv_bfloat162* pm = reinterpret_cast<__nv_bfloat162*>(g_xm);
    __nv_bfloat162* pl = reinterpret_cast<__nv_bfloat162*>(g_xl);
    ph[2 * i]     = __nv_bfloat162(h[0], h[1]);
    ph[2 * i + 1] = __nv_bfloat162(h[2], h[3]);
    pm[2 * i]     = __nv_bfloat162(m4[0], m4[1]);
    pm[2 * i + 1] = __nv_bfloat162(m4[2], m4[3]);
    pl[2 * i]     = __nv_bfloat162(l[0], l[1]);
    pl[2 * i + 1] = __nv_bfloat162(l[2], l[3]);
}

__global__ __launch_bounds__(256)
void split_w_kernel(const float* __restrict__ Wb) {
    int idx = blockIdx.x * 256 + threadIdx.x;   // n*I + k
    int n = idx >> 9;
    int k = idx & (I_ - 1);
    int nb = n >> 8;
    int hb = n & (HB_ - 1);
    float a = Wb[((size_t)nb * I_ + k) * HB_ + hb];
    __nv_bfloat16 hh = __float2bfloat16_rn(a);
    float r = a - __bfloat162float(hh);
    __nv_bfloat16 mm = __float2bfloat16_rn(r);
    float r2 = r - __bfloat162float(mm);
    g_wh[idx] = hh;
    g_wm[idx] = mm;
    g_wl[idx] = __float2bfloat16_rn(r2);
}

// ---------------------------------------------------------------------------
// mma.sync bf16 GEMM (sm_80 baseline PTX — no 'a'-gated features)
// u[m, n] = sum of 6 split products; m = b*T + t
// CTA tile 128x128, warp tile 64x32, K-chunk 16, 3-stage cp.async pipeline
// ---------------------------------------------------------------------------
#define NCHUNK (I_ / 16)          // 32
#define STAGE_BYTES 24576         // 3 A parts (4KB) + 3 B parts (4KB)
#define SMEM_GEMM (3 * STAGE_BYTES)   // 73728

__device__ __forceinline__ uint32_t smem_u32(const void* p) {
    uint32_t a;
    asm("{ .reg .u64 t; cvta.to.shared.u64 t, %1; cvt.u32.u64 %0, t; }"
        : "=r"(a) : "l"(p));
    return a;
}
// XOR swizzle: tile row r (0..127), 16B half h -> byte offset in 4KB part
__device__ __forceinline__ uint32_t sw_off(int r, int h) {
    return (uint32_t)(r * 32 + ((h ^ ((r >> 2) & 1)) << 4));
}

#define CP16(dst, src) \
    asm volatile("cp.async.cg.shared.global [%0], [%1], 16;" \
                 :: "r"(dst), "l"(src))
#define CPCOMMIT() asm volatile("cp.async.commit_group;" ::: "memory")
#define CPWAIT(n)  asm volatile("cp.async.wait_group %0;" :: "n"(n) : "memory")

#define LDSM4(r0, r1, r2, r3, addr) \
    asm volatile("ldmatrix.sync.aligned.m8n8.x4.shared.b16 {%0,%1,%2,%3}, [%4];" \
                 : "=r"(r0), "=r"(r1), "=r"(r2), "=r"(r3) : "r"(addr))

#define MMA16816(d, a, b) \
    asm volatile("mma.sync.aligned.m16n8k16.row.col.f32.bf16.bf16.f32 " \
                 "{%0,%1,%2,%3}, {%4,%5,%6,%7}, {%8,%9}, {%0,%1,%2,%3};" \
                 : "+f"((d)[0]), "+f"((d)[1]), "+f"((d)[2]), "+f"((d)[3]) \
                 : "r"((a)[0]), "r"((a)[1]), "r"((a)[2]), "r"((a)[3]), \
                   "r"((b)[0]), "r"((b)[1]))

__global__ __launch_bounds__(256)
void gemm_mma_kernel() {
    extern __shared__ char smem[];
    const uint32_t sb = smem_u32(smem);

    const int tid  = threadIdx.x;
    const int wid  = tid >> 5;
    const int lane = tid & 31;
    const int n0 = blockIdx.x * 128;   // over H (8) — fast dim for A L2 reuse
    const int m0 = blockIdx.y * 128;   // over B*T (1024)

    const int wm_off = (wid & 1) * 64;
    const int wn_off = (wid >> 1) * 32;

    const __nv_bfloat16* XP[3] = {g_xh, g_xm, g_xl};
    const __nv_bfloat16* WP[3] = {g_wh, g_wm, g_wl};

    // cp.async mapping: thread -> (row, 16B half) within a 128x16 part
    const int ldr = tid >> 1;
    const int ldh = tid & 1;
    const uint32_t ld_dst = sw_off(ldr, ldh);
    const size_t srcA = (size_t)(m0 + ldr) * I_ + ldh * 8;   // + k0 later
    const size_t srcB = (size_t)(n0 + ldr) * I_ + ldh * 8;

    // ldmatrix per-thread offsets (within a 4KB part)
    uint32_t aoff[4], boff[2];
    {
        int arow = wm_off + (lane & 15);
        int ah   = (lane >> 4) & 1;
#pragma unroll
        for (int i = 0; i < 4; i++) aoff[i] = sw_off(arow + 16 * i, ah);
        int brow = wn_off + (lane & 7) + ((lane >> 4) << 3);
        int bh   = (lane >> 3) & 1;
#pragma unroll
        for (int j = 0; j < 2; j++) boff[j] = sw_off(brow + 16 * j, bh);
    }

    float acc[4][4][4];
#pragma unroll
    for (int i = 0; i < 4; i++)
#pragma unroll
        for (int j = 0; j < 4; j++)
#pragma unroll
            for (int q = 0; q < 4; q++) acc[i][j][q] = 0.f;

    // ---- pipeline ----
    auto load_chunk = [&](int c, int s) {
        const int k0 = c * 16;
        const uint32_t base = sb + s * STAGE_BYTES;
#pragma unroll
        for (int p = 0; p < 3; p++)
            CP16(base + p * 4096 + ld_dst, XP[p] + srcA + k0);
#pragma unroll
        for (int p = 0; p < 3; p++)
            CP16(base + 12288 + p * 4096 + ld_dst, WP[p] + srcB + k0);
    };

    load_chunk(0, 0); CPCOMMIT();
    load_chunk(1, 1); CPCOMMIT();

    for (int c = 0; c < NCHUNK; c++) {
        if (c + 2 < NCHUNK) { load_chunk(c + 2, (c + 2) % 3); CPCOMMIT(); }
        if (c < NCHUNK - 2)      { CPWAIT(2); }
        else if (c == NCHUNK - 2) { CPWAIT(1); }
        else                      { CPWAIT(0); }
        __syncthreads();

        const uint32_t aBase = sb + (c % 3) * STAGE_BYTES;
        const uint32_t bBase = aBase + 12288;

        // load all B fragments (3 parts x 4 n-frags x 2 regs)
        uint32_t bf[3][4][2];
#pragma unroll
        for (int p = 0; p < 3; p++)
#pragma unroll
            for (int j2 = 0; j2 < 2; j2++) {
                uint32_t r0, r1, r2, r3;
                LDSM4(r0, r1, r2, r3, bBase + p * 4096 + boff[j2]);
                bf[p][2 * j2][0] = r0; bf[p][2 * j2][1] = r1;
                bf[p][2 * j2 + 1][0] = r2; bf[p][2 * j2 + 1][1] = r3;
            }

        // A part groups: xh -> {wh,wm,wl}; xm -> {wh,wm}; xl -> {wh}
#pragma unroll
        for (int pa = 0; pa < 3; pa++) {
            uint32_t af[4][4];
#pragma unroll
            for (int i = 0; i < 4; i++)
                LDSM4(af[i][0], af[i][1], af[i][2], af[i][3],
                      aBase + pa * 4096 + aoff[i]);
            const int nb = 3 - pa;
#pragma unroll
            for (int pb = 0; pb < 3; pb++) {
                if (pb >= nb) break;
#pragma unroll
                for (int i = 0; i < 4; i++)
#pragma unroll
                    for (int j = 0; j < 4; j++)
                        MMA16816(acc[i][j], af[i], bf[pb][j]);
            }
        }
        __syncthreads();
    }

    // ---- epilogue: write u[t][b][h] ----
    const int g  = lane >> 2;
    const int tq = lane & 3;
    const int colb = n0 + wn_off + 2 * tq;
#pragma unroll
    for (int i = 0; i < 4; i++)
#pragma unroll
        for (int h2 = 0; h2 < 2; h2++) {
            int m = m0 + wm_off + 16 * i + 8 * h2 + g;
            int b = m >> 9;          // / T_
            int t = m & (T_ - 1);
            float* base = g_u + ((size_t)t * B_ + b) * H_ + colb;
#pragma unroll
            for (int j = 0; j < 4; j++) {
                float2 v = make_float2(acc[i][j][2 * h2], acc[i][j][2 * h2 + 1]);
                *reinterpret_cast<float2*>(base + 8 * j) = v;
            }
        }
}

// ---------------------------------------------------------------------------
// Phase 2: per-neuron LIF recurrence over T (unchanged, passing)
// ---------------------------------------------------------------------------
__global__ __launch_bounds__(256)
void recur_kernel(const float* __restrict__ v0,
                  const float* __restrict__ tau_n,
                  const float* __restrict__ tau_m) {
    const int idx = blockIdx.x * blockDim.x + threadIdx.x;
    const int h = idx & (H_ - 1);

    const float beta  = 1.f / (1.f + expf(-tau_n[h]));
    const float alpha = 1.f / (1.f + expf(-tau_m[h]));
    const float omb = 1.f - beta;
    const float oma = 1.f - alpha;

    float d = 0.f, v = v0[idx], s = 0.f, acc = 0.f;
    const float* up = g_u + idx;
    const size_t stride = (size_t)B_ * H_;

#pragma unroll 4
    for (int t = 0; t < T_; t++) {
        float u = up[(size_t)t * stride];
        d = beta * d + omb * u;
        v = alpha * v + oma * d - s;
        s = (v > 1.0f) ? 1.0f : 0.0f;
        if (t >= T_ / 2) acc += s;
    }
    g_acc[idx] = acc;
}

// ---------------------------------------------------------------------------
// Phase 3: out = acc @ W_out + b_out
// ---------------------------------------------------------------------------
__global__ __launch_bounds__(O_)
void out_kernel(const float* __restrict__ Wout,
                const float* __restrict__ bout,
                float* __restrict__ out) {
    __shared__ float sacc[H_];
    const int b = blockIdx.x;
    const int o = threadIdx.x;
    for (int h = o; h < H_; h += O_) sacc[h] = g_acc[b * H_ + h];
    __syncthreads();
    float sum = bout[o];
#pragma unroll 8
    for (int h = 0; h < H_; h++)
        sum = fmaf(sacc[h], Wout[h * O_ + o], sum);
    out[b * O_ + o] = sum;
}

// ---------------------------------------------------------------------------
extern "C" void kernel_launch(void* const* d_in, const int* in_sizes, int n_in,
                              void* d_out, int out_size) {
    const float* x     = (const float*)d_in[0];
    const float* v0    = (const float*)d_in[1];
    const float* Wb    = (const float*)d_in[2];
    const float* tau_n = (const float*)d_in[3];
    const float* tau_m = (const float*)d_in[4];
    const float* Wout  = (const float*)d_in[5];
    const float* bout  = (const float*)d_in[6];
    float* out = (float*)d_out;
    (void)in_sizes; (void)n_in; (void)out_size;

    static bool attr_set = false;
    if (!attr_set) {
        cudaFuncSetAttribute(gemm_mma_kernel,
                             cudaFuncAttributeMaxDynamicSharedMemorySize,
                             SMEM_GEMM);
        attr_set = true;
    }

    split_x_kernel<<<(M_ * I_ / 4) / 256, 256>>>(x);
    split_w_kernel<<<(H_ * I_) / 256, 256>>>(Wb);

    dim3 ggrid(H_ / 128, M_ / 128);   // (8, 1024)
    gemm_mma_kernel<<<ggrid, 256, SMEM_GEMM>>>();

    recur_kernel<<<(B_ * H_) / 256, 256>>>(v0, tau_n, tau_m);
    out_kernel<<<B_, O_>>>(Wout, bout, out);
}

// round 8
// speedup vs baseline: 1.4006x; 1.0217x over previous
#include <cuda_runtime.h>
#include <cuda_bf16.h>
#include <cstdint>
#include <cstddef>

#define B_  256
#define T_  512
#define I_  512
#define H_  1024
#define HB_ 256
#define O_  128
#define M_  (B_ * T_)     // 131072

// ---------------------------------------------------------------------------
// Scratch (device globals; allocation is forbidden)
// ---------------------------------------------------------------------------
__device__ __align__(1024) float g_u[(size_t)T_ * B_ * H_];       // 512 MB
__device__ __align__(1024) float g_acc[B_ * H_];
__device__ __align__(1024) __nv_bfloat16 g_xh[(size_t)M_ * I_];   // 128 MB each
__device__ __align__(1024) __nv_bfloat16 g_xm[(size_t)M_ * I_];
__device__ __align__(1024) __nv_bfloat16 g_xl[(size_t)M_ * I_];
__device__ __align__(1024) __nv_bfloat16 g_wh[H_ * I_];           // 1 MB each, [n][k]
__device__ __align__(1024) __nv_bfloat16 g_wm[H_ * I_];
__device__ __align__(1024) __nv_bfloat16 g_wl[H_ * I_];

// ---------------------------------------------------------------------------
// Split kernels: x (and W) -> bf16 high/mid/low parts
// ---------------------------------------------------------------------------
__global__ __launch_bounds__(256)
void split_x_kernel(const float* __restrict__ x) {
    size_t i = (size_t)blockIdx.x * blockDim.x + threadIdx.x;  // float4 index
    float4 v = reinterpret_cast<const float4*>(x)[i];
    float f[4] = {v.x, v.y, v.z, v.w};
    __nv_bfloat16 h[4], m4[4], l[4];
#pragma unroll
    for (int j = 0; j < 4; j++) {
        float a = f[j];
        __nv_bfloat16 hh = __float2bfloat16_rn(a);
        float r = a - __bfloat162float(hh);
        __nv_bfloat16 mm = __float2bfloat16_rn(r);
        float r2 = r - __bfloat162float(mm);
        h[j] = hh; m4[j] = mm; l[j] = __float2bfloat16_rn(r2);
    }
    __nv_bfloat162* ph = reinterpret_cast<__nv_bfloat162*>(g_xh);
    __nv_bfloat162* pm = reinterpret_cast<__nv_bfloat162*>(g_xm);
    __nv_bfloat162* pl = reinterpret_cast<__nv_bfloat162*>(g_xl);
    ph[2 * i]     = __nv_bfloat162(h[0], h[1]);
    ph[2 * i + 1] = __nv_bfloat162(h[2], h[3]);
    pm[2 * i]     = __nv_bfloat162(m4[0], m4[1]);
    pm[2 * i + 1] = __nv_bfloat162(m4[2], m4[3]);
    pl[2 * i]     = __nv_bfloat162(l[0], l[1]);
    pl[2 * i + 1] = __nv_bfloat162(l[2], l[3]);
}

__global__ __launch_bounds__(256)
void split_w_kernel(const float* __restrict__ Wb) {
    int idx = blockIdx.x * 256 + threadIdx.x;   // n*I + k
    int n = idx >> 9;
    int k = idx & (I_ - 1);
    int nb = n >> 8;
    int hb = n & (HB_ - 1);
    float a = Wb[((size_t)nb * I_ + k) * HB_ + hb];
    __nv_bfloat16 hh = __float2bfloat16_rn(a);
    float r = a - __bfloat162float(hh);
    __nv_bfloat16 mm = __float2bfloat16_rn(r);
    float r2 = r - __bfloat162float(mm);
    g_wh[idx] = hh;
    g_wm[idx] = mm;
    g_wl[idx] = __float2bfloat16_rn(r2);
}

// no-op probe so the GEMM sits at absolute launch index 3 (the ncu capture slot)
__global__ void probe_kernel() {}

// ---------------------------------------------------------------------------
// mma.sync bf16 GEMM. CTA tile 128x128, warp tile 64x32 (2m x 4n warps),
// K-chunk 32, 3-stage cp.async ring, ONE __syncthreads per chunk.
// ---------------------------------------------------------------------------
#define KC 32
#define NCHUNK (I_ / KC)           // 16
#define PART_BYTES (128 * KC * 2)  // 8192 (128 rows x 64B)
#define STAGE_BYTES (6 * PART_BYTES)   // 49152: 3 A parts + 3 B parts
#define SMEM_GEMM (3 * STAGE_BYTES)    // 147456

__device__ __forceinline__ uint32_t smem_u32(const void* p) {
    uint32_t a;
    asm("{ .reg .u64 t; cvta.to.shared.u64 t, %1; cvt.u32.u64 %0, t; }"
        : "=r"(a) : "l"(p));
    return a;
}
// 64B-row swizzle: row r (0..127), 16B slot h (0..3).
// Per-ldmatrix-phase (8 lanes, rows r..r+7, fixed h): even rows map to 4
// distinct slots in bank-phase 0, odd rows in phase 1 -> conflict-free.
__device__ __forceinline__ uint32_t sw64(int r, int h) {
    return (uint32_t)(r * 64 + ((h ^ ((r >> 1) & 3)) << 4));
}

#define CP16(dst, src) \
    asm volatile("cp.async.cg.shared.global [%0], [%1], 16;" \
                 :: "r"(dst), "l"(src))
#define CPCOMMIT() asm volatile("cp.async.commit_group;" ::: "memory")
#define CPWAIT(n)  asm volatile("cp.async.wait_group %0;" :: "n"(n) : "memory")

#define LDSM4(r0, r1, r2, r3, addr) \
    asm volatile("ldmatrix.sync.aligned.m8n8.x4.shared.b16 {%0,%1,%2,%3}, [%4];" \
                 : "=r"(r0), "=r"(r1), "=r"(r2), "=r"(r3) : "r"(addr))

#define MMA16816(d, a, b) \
    asm volatile("mma.sync.aligned.m16n8k16.row.col.f32.bf16.bf16.f32 " \
                 "{%0,%1,%2,%3}, {%4,%5,%6,%7}, {%8,%9}, {%0,%1,%2,%3};" \
                 : "+f"((d)[0]), "+f"((d)[1]), "+f"((d)[2]), "+f"((d)[3]) \
                 : "r"((a)[0]), "r"((a)[1]), "r"((a)[2]), "r"((a)[3]), \
                   "r"((b)[0]), "r"((b)[1]))

__global__ __launch_bounds__(256)
void gemm_mma_kernel() {
    extern __shared__ char smem[];
    const uint32_t sb = smem_u32(smem);

    const int tid  = threadIdx.x;
    const int wid  = tid >> 5;
    const int lane = tid & 31;
    const int n0 = blockIdx.x * 128;   // over H (8) — fast dim for A L2 reuse
    const int m0 = blockIdx.y * 128;   // over B*T (1024)

    const int wm_off = (wid & 1) * 64;
    const int wn_off = (wid >> 1) * 32;

    const __nv_bfloat16* XP[3] = {g_xh, g_xm, g_xl};
    const __nv_bfloat16* WP[3] = {g_wh, g_wm, g_wl};

    // cp.async mapping: 128 rows x 4 sixteen-byte slots per part, 2 units/thread
    const int ldr = tid >> 2;          // row 0..63 (unit 0); +64 for unit 1
    const int ldh = tid & 3;           // slot 0..3
    const uint32_t dst0 = sw64(ldr, ldh);           // unit 1: +64*64 = +4096
    const size_t srcA = (size_t)(m0 + ldr) * I_ + ldh * 8;   // +k0, +64*I_ for unit 1
    const size_t srcB = (size_t)(n0 + ldr) * I_ + ldh * 8;

    float acc[4][4][4];
#pragma unroll
    for (int i = 0; i < 4; i++)
#pragma unroll
        for (int j = 0; j < 4; j++)
#pragma unroll
            for (int q = 0; q < 4; q++) acc[i][j][q] = 0.f;

    auto load_chunk = [&](int c, int s) {
        const int k0 = c * KC;
        const uint32_t base = sb + s * STAGE_BYTES;
#pragma unroll
        for (int p = 0; p < 3; p++) {
            CP16(base + p * PART_BYTES + dst0,        XP[p] + srcA + k0);
            CP16(base + p * PART_BYTES + dst0 + 4096, XP[p] + srcA + k0 + (size_t)64 * I_);
        }
#pragma unroll
        for (int p = 0; p < 3; p++) {
            CP16(base + (3 + p) * PART_BYTES + dst0,        WP[p] + srcB + k0);
            CP16(base + (3 + p) * PART_BYTES + dst0 + 4096, WP[p] + srcB + k0 + (size_t)64 * I_);
        }
    };

    load_chunk(0, 0); CPCOMMIT();
    load_chunk(1, 1); CPCOMMIT();

    const int arow = wm_off + (lane & 15);
    const int ahl  = (lane >> 4) & 1;               // k 16B-slot low bit
    const int brow = wn_off + (lane & 7) + ((lane >> 4) << 3);
    const int bhl  = (lane >> 3) & 1;

    for (int c = 0; c < NCHUNK; c++) {
        if (c < NCHUNK - 1) { CPWAIT(1); } else { CPWAIT(0); }
        __syncthreads();
        if (c + 2 < NCHUNK) { load_chunk(c + 2, (c + 2) % 3); CPCOMMIT(); }

        const uint32_t aBase = sb + (c % 3) * STAGE_BYTES;
        const uint32_t bBase = aBase + 3 * PART_BYTES;

#pragma unroll
        for (int kk2 = 0; kk2 < 2; kk2++) {         // two k16 sub-steps
            const int ha = kk2 * 2 + ahl;
            const int hb = kk2 * 2 + bhl;

            uint32_t bf[3][4][2];
#pragma unroll
            for (int p = 0; p < 3; p++)
#pragma unroll
                for (int j2 = 0; j2 < 2; j2++) {
                    uint32_t r0, r1, r2, r3;
                    LDSM4(r0, r1, r2, r3,
                          bBase + p * PART_BYTES + sw64(brow + 16 * j2, hb));
                    bf[p][2 * j2][0] = r0;     bf[p][2 * j2][1] = r1;
                    bf[p][2 * j2 + 1][0] = r2; bf[p][2 * j2 + 1][1] = r3;
                }

            // product groups: xh·{wh,wm,wl}; xm·{wh,wm}; xl·{wh}
#pragma unroll
            for (int pa = 0; pa < 3; pa++) {
                uint32_t af[4][4];
#pragma unroll
                for (int i = 0; i < 4; i++)
                    LDSM4(af[i][0], af[i][1], af[i][2], af[i][3],
                          aBase + pa * PART_BYTES + sw64(arow + 16 * i, ha));
                const int nb = 3 - pa;
#pragma unroll
                for (int pb = 0; pb < 3; pb++) {
                    if (pb >= nb) break;
#pragma unroll
                    for (int i = 0; i < 4; i++)
#pragma unroll
                        for (int j = 0; j < 4; j++)
                            MMA16816(acc[i][j], af[i], bf[pb][j]);
                }
            }
        }
    }

    // ---- epilogue: write u[t][b][h] (sector-coalesced float2 stores) ----
    const int g  = lane >> 2;
    const int tq = lane & 3;
    const int colb = n0 + wn_off + 2 * tq;
#pragma unroll
    for (int i = 0; i < 4; i++)
#pragma unroll
        for (int h2 = 0; h2 < 2; h2++) {
            int m = m0 + wm_off + 16 * i + 8 * h2 + g;
            int b = m >> 9;          // / T_
            int t = m & (T_ - 1);
            float* base = g_u + ((size_t)t * B_ + b) * H_ + colb;
#pragma unroll
            for (int j = 0; j < 4; j++) {
                float2 v = make_float2(acc[i][j][2 * h2], acc[i][j][2 * h2 + 1]);
                *reinterpret_cast<float2*>(base + 8 * j) = v;
            }
        }
}

// ---------------------------------------------------------------------------
// Phase 2: per-neuron LIF recurrence over T
// ---------------------------------------------------------------------------
__global__ __launch_bounds__(256)
void recur_kernel(const float* __restrict__ v0,
                  const float* __restrict__ tau_n,
                  const float* __restrict__ tau_m) {
    const int idx = blockIdx.x * blockDim.x + threadIdx.x;
    const int h = idx & (H_ - 1);

    const float beta  = 1.f / (1.f + expf(-tau_n[h]));
    const float alpha = 1.f / (1.f + expf(-tau_m[h]));
    const float omb = 1.f - beta;
    const float oma = 1.f - alpha;

    float d = 0.f, v = v0[idx], s = 0.f, acc = 0.f;
    const float* up = g_u + idx;
    const size_t stride = (size_t)B_ * H_;

#pragma unroll 4
    for (int t = 0; t < T_; t++) {
        float u = up[(size_t)t * stride];
        d = beta * d + omb * u;
        v = alpha * v + oma * d - s;
        s = (v > 1.0f) ? 1.0f : 0.0f;
        if (t >= T_ / 2) acc += s;
    }
    g_acc[idx] = acc;
}

// ---------------------------------------------------------------------------
// Phase 3: out = acc @ W_out + b_out
// ---------------------------------------------------------------------------
__global__ __launch_bounds__(O_)
void out_kernel(const float* __restrict__ Wout,
                const float* __restrict__ bout,
                float* __restrict__ out) {
    __shared__ float sacc[H_];
    const int b = blockIdx.x;
    const int o = threadIdx.x;
    for (int h = o; h < H_; h += O_) sacc[h] = g_acc[b * H_ + h];
    __syncthreads();
    float sum = bout[o];
#pragma unroll 8
    for (int h = 0; h < H_; h++)
        sum = fmaf(sacc[h], Wout[h * O_ + o], sum);
    out[b * O_ + o] = sum;
}

// ---------------------------------------------------------------------------
extern "C" void kernel_launch(void* const* d_in, const int* in_sizes, int n_in,
                              void* d_out, int out_size) {
    const float* x     = (const float*)d_in[0];
    const float* v0    = (const float*)d_in[1];
    const float* Wb    = (const float*)d_in[2];
    const float* tau_n = (const float*)d_in[3];
    const float* tau_m = (const float*)d_in[4];
    const float* Wout  = (const float*)d_in[5];
    const float* bout  = (const float*)d_in[6];
    float* out = (float*)d_out;
    (void)in_sizes; (void)n_in; (void)out_size;

    static bool attr_set = false;
    if (!attr_set) {
        cudaFuncSetAttribute(gemm_mma_kernel,
                             cudaFuncAttributeMaxDynamicSharedMemorySize,
                             SMEM_GEMM);
        attr_set = true;
    }

    split_x_kernel<<<(M_ * I_ / 4) / 256, 256>>>(x);   // launch 0
    split_w_kernel<<<(H_ * I_) / 256, 256>>>(Wb);      // launch 1
    probe_kernel<<<1, 32>>>();                          // launch 2 (profil. slot pad)

    dim3 ggrid(H_ / 128, M_ / 128);   // (8, 1024)
    gemm_mma_kernel<<<ggrid, 256, SMEM_GEMM>>>();      // launch 3 <- ncu capture

    recur_kernel<<<(B_ * H_) / 256, 256>>>(v0, tau_n, tau_m);
    out_kernel<<<B_, O_>>>(Wout, bout, out);
}

// round 9
// speedup vs baseline: 2.6848x; 1.9169x over previous
#include <cuda_runtime.h>
#include <cuda_fp16.h>
#include <cstdint>
#include <cstddef>

#define B_  256
#define T_  512
#define I_  512
#define H_  1024
#define HB_ 256
#define O_  128
#define M_  (B_ * T_)     // 131072

// ---------------------------------------------------------------------------
// Scratch (device globals; allocation is forbidden)
// ---------------------------------------------------------------------------
__device__ __align__(1024) float g_u[(size_t)T_ * B_ * H_];   // 512 MB
__device__ __align__(1024) float g_acc[B_ * H_];
__device__ __align__(1024) __half g_xh[(size_t)M_ * I_];      // 128 MB each
__device__ __align__(1024) __half g_xm[(size_t)M_ * I_];
__device__ __align__(1024) __half g_wh[H_ * I_];              // 1 MB each, [n][k]
__device__ __align__(1024) __half g_wm[H_ * I_];

// ---------------------------------------------------------------------------
// Split kernels: fp16 two-term split x = h + m  (h=fl16(x), m=fl16(x-h))
// ---------------------------------------------------------------------------
__global__ __launch_bounds__(256)
void split_x_kernel(const float* __restrict__ x) {
    size_t i = (size_t)blockIdx.x * blockDim.x + threadIdx.x;  // float4 index
    float4 v = reinterpret_cast<const float4*>(x)[i];
    float f[4] = {v.x, v.y, v.z, v.w};
    __half h[4], m4[4];
#pragma unroll
    for (int j = 0; j < 4; j++) {
        float a = f[j];
        __half hh = __float2half_rn(a);
        float r = a - __half2float(hh);
        h[j] = hh;
        m4[j] = __float2half_rn(r);
    }
    __half2* ph = reinterpret_cast<__half2*>(g_xh);
    __half2* pm = reinterpret_cast<__half2*>(g_xm);
    ph[2 * i]     = __half2(h[0], h[1]);
    ph[2 * i + 1] = __half2(h[2], h[3]);
    pm[2 * i]     = __half2(m4[0], m4[1]);
    pm[2 * i + 1] = __half2(m4[2], m4[3]);
}

__global__ __launch_bounds__(256)
void split_w_kernel(const float* __restrict__ Wb) {
    int idx = blockIdx.x * 256 + threadIdx.x;   // n*I + k
    int n = idx >> 9;
    int k = idx & (I_ - 1);
    int nb = n >> 8;
    int hb = n & (HB_ - 1);
    float a = Wb[((size_t)nb * I_ + k) * HB_ + hb];
    __half hh = __float2half_rn(a);
    float r = a - __half2float(hh);
    g_wh[idx] = hh;
    g_wm[idx] = __float2half_rn(r);
}

// no-op probe so the GEMM sits at absolute launch index 3 (the ncu capture slot)
__global__ void probe_kernel() {}

// ---------------------------------------------------------------------------
// mma.sync fp16 GEMM, 3 products (hh, hm, mh).
// CTA tile 128x128, warp tile 64x32 (2m x 4n warps), K-chunk 32,
// 3-stage cp.async ring, ONE __syncthreads per chunk, 2 CTAs/SM.
// ---------------------------------------------------------------------------
#define KC 32
#define NCHUNK (I_ / KC)           // 16
#define PART_BYTES (128 * KC * 2)  // 8192 (128 rows x 64B)
#define STAGE_BYTES (4 * PART_BYTES)   // 32768: 2 A parts + 2 B parts
#define SMEM_GEMM (3 * STAGE_BYTES)    // 98304 -> 2 CTAs/SM

__device__ __forceinline__ uint32_t smem_u32(const void* p) {
    uint32_t a;
    asm("{ .reg .u64 t; cvta.to.shared.u64 t, %1; cvt.u32.u64 %0, t; }"
        : "=r"(a) : "l"(p));
    return a;
}
// 64B-row swizzle: row r (0..127), 16B slot h (0..3) — conflict-free per phase
__device__ __forceinline__ uint32_t sw64(int r, int h) {
    return (uint32_t)(r * 64 + ((h ^ ((r >> 1) & 3)) << 4));
}

#define CP16(dst, src) \
    asm volatile("cp.async.cg.shared.global [%0], [%1], 16;" \
                 :: "r"(dst), "l"(src))
#define CPCOMMIT() asm volatile("cp.async.commit_group;" ::: "memory")
#define CPWAIT(n)  asm volatile("cp.async.wait_group %0;" :: "n"(n) : "memory")

#define LDSM4(r0, r1, r2, r3, addr) \
    asm volatile("ldmatrix.sync.aligned.m8n8.x4.shared.b16 {%0,%1,%2,%3}, [%4];" \
                 : "=r"(r0), "=r"(r1), "=r"(r2), "=r"(r3) : "r"(addr))

#define MMA16816(d, a, b) \
    asm volatile("mma.sync.aligned.m16n8k16.row.col.f32.f16.f16.f32 " \
                 "{%0,%1,%2,%3}, {%4,%5,%6,%7}, {%8,%9}, {%0,%1,%2,%3};" \
                 : "+f"((d)[0]), "+f"((d)[1]), "+f"((d)[2]), "+f"((d)[3]) \
                 : "r"((a)[0]), "r"((a)[1]), "r"((a)[2]), "r"((a)[3]), \
                   "r"((b)[0]), "r"((b)[1]))

__global__ __launch_bounds__(256, 2)
void gemm_mma_kernel() {
    extern __shared__ char smem[];
    const uint32_t sb = smem_u32(smem);

    const int tid  = threadIdx.x;
    const int wid  = tid >> 5;
    const int lane = tid & 31;
    const int n0 = blockIdx.x * 128;   // over H (8) — fast dim for A L2 reuse
    const int m0 = blockIdx.y * 128;   // over B*T (1024)

    const int wm_off = (wid & 1) * 64;
    const int wn_off = (wid >> 1) * 32;

    const __half* XP[2] = {g_xh, g_xm};
    const __half* WP[2] = {g_wh, g_wm};

    // cp.async mapping: 128 rows x 4 sixteen-byte slots per part, 2 units/thread
    const int ldr = tid >> 2;          // row 0..63 (unit 0); +64 for unit 1
    const int ldh = tid & 3;           // slot 0..3
    const uint32_t dst0 = sw64(ldr, ldh);           // unit 1: +4096
    const size_t srcA = (size_t)(m0 + ldr) * I_ + ldh * 8;
    const size_t srcB = (size_t)(n0 + ldr) * I_ + ldh * 8;

    float acc[4][4][4];
#pragma unroll
    for (int i = 0; i < 4; i++)
#pragma unroll
        for (int j = 0; j < 4; j++)
#pragma unroll
            for (int q = 0; q < 4; q++) acc[i][j][q] = 0.f;

    auto load_chunk = [&](int c, int s) {
        const int k0 = c * KC;
        const uint32_t base = sb + s * STAGE_BYTES;
#pragma unroll
        for (int p = 0; p < 2; p++) {
            CP16(base + p * PART_BYTES + dst0,        XP[p] + srcA + k0);
            CP16(base + p * PART_BYTES + dst0 + 4096, XP[p] + srcA + k0 + (size_t)64 * I_);
        }
#pragma unroll
        for (int p = 0; p < 2; p++) {
            CP16(base + (2 + p) * PART_BYTES + dst0,        WP[p] + srcB + k0);
            CP16(base + (2 + p) * PART_BYTES + dst0 + 4096, WP[p] + srcB + k0 + (size_t)64 * I_);
        }
    };

    load_chunk(0, 0); CPCOMMIT();
    load_chunk(1, 1); CPCOMMIT();

    const int arow = wm_off + (lane & 15);
    const int ahl  = (lane >> 4) & 1;               // k 16B-slot low bit
    const int brow = wn_off + (lane & 7) + ((lane >> 4) << 3);
    const int bhl  = (lane >> 3) & 1;

    for (int c = 0; c < NCHUNK; c++) {
        if (c < NCHUNK - 1) { CPWAIT(1); } else { CPWAIT(0); }
        __syncthreads();
        if (c + 2 < NCHUNK) { load_chunk(c + 2, (c + 2) % 3); CPCOMMIT(); }

        const uint32_t aBase = sb + (c % 3) * STAGE_BYTES;
        const uint32_t bBase = aBase + 2 * PART_BYTES;

#pragma unroll
        for (int kk2 = 0; kk2 < 2; kk2++) {         // two k16 sub-steps
            const int ha = kk2 * 2 + ahl;
            const int hb = kk2 * 2 + bhl;

            // B fragments: 2 parts x 4 n-frags x 2 regs
            uint32_t bf[2][4][2];
#pragma unroll
            for (int p = 0; p < 2; p++)
#pragma unroll
                for (int j2 = 0; j2 < 2; j2++) {
                    uint32_t r0, r1, r2, r3;
                    LDSM4(r0, r1, r2, r3,
                          bBase + p * PART_BYTES + sw64(brow + 16 * j2, hb));
                    bf[p][2 * j2][0] = r0;     bf[p][2 * j2][1] = r1;
                    bf[p][2 * j2 + 1][0] = r2; bf[p][2 * j2 + 1][1] = r3;
                }

            // A high part: products hh + hm
            {
                uint32_t af[4][4];
#pragma unroll
                for (int i = 0; i < 4; i++)
                    LDSM4(af[i][0], af[i][1], af[i][2], af[i][3],
                          aBase + sw64(arow + 16 * i, ha));
#pragma unroll
                for (int i = 0; i < 4; i++)
#pragma unroll
                    for (int j = 0; j < 4; j++)
                        MMA16816(acc[i][j], af[i], bf[0][j]);
#pragma unroll
                for (int i = 0; i < 4; i++)
#pragma unroll
                    for (int j = 0; j < 4; j++)
                        MMA16816(acc[i][j], af[i], bf[1][j]);
            }
            // A mid part: product mh
            {
                uint32_t af[4][4];
#pragma unroll
                for (int i = 0; i < 4; i++)
                    LDSM4(af[i][0], af[i][1], af[i][2], af[i][3],
                          aBase + PART_BYTES + sw64(arow + 16 * i, ha));
#pragma unroll
                for (int i = 0; i < 4; i++)
#pragma unroll
                    for (int j = 0; j < 4; j++)
                        MMA16816(acc[i][j], af[i], bf[0][j]);
            }
        }
    }

    // ---- epilogue: write u[t][b][h] ----
    const int g  = lane >> 2;
    const int tq = lane & 3;
    const int colb = n0 + wn_off + 2 * tq;
#pragma unroll
    for (int i = 0; i < 4; i++)
#pragma unroll
        for (int h2 = 0; h2 < 2; h2++) {
            int m = m0 + wm_off + 16 * i + 8 * h2 + g;
            int b = m >> 9;          // / T_
            int t = m & (T_ - 1);
            float* base = g_u + ((size_t)t * B_ + b) * H_ + colb;
#pragma unroll
            for (int j = 0; j < 4; j++) {
                float2 v = make_float2(acc[i][j][2 * h2], acc[i][j][2 * h2 + 1]);
                *reinterpret_cast<float2*>(base + 8 * j) = v;
            }
        }
}

// ---------------------------------------------------------------------------
// Phase 2: per-neuron LIF recurrence over T
// ---------------------------------------------------------------------------
__global__ __launch_bounds__(256)
void recur_kernel(const float* __restrict__ v0,
                  const float* __restrict__ tau_n,
                  const float* __restrict__ tau_m) {
    const int idx = blockIdx.x * blockDim.x + threadIdx.x;
    const int h = idx & (H_ - 1);

    const float beta  = 1.f / (1.f + expf(-tau_n[h]));
    const float alpha = 1.f / (1.f + expf(-tau_m[h]));
    const float omb = 1.f - beta;
    const float oma = 1.f - alpha;

    float d = 0.f, v = v0[idx], s = 0.f, acc = 0.f;
    const float* up = g_u + idx;
    const size_t stride = (size_t)B_ * H_;

#pragma unroll 4
    for (int t = 0; t < T_; t++) {
        float u = up[(size_t)t * stride];
        d = beta * d + omb * u;
        v = alpha * v + oma * d - s;
        s = (v > 1.0f) ? 1.0f : 0.0f;
        if (t >= T_ / 2) acc += s;
    }
    g_acc[idx] = acc;
}

// ---------------------------------------------------------------------------
// Phase 3: out = acc @ W_out + b_out
// ---------------------------------------------------------------------------
__global__ __launch_bounds__(O_)
void out_kernel(const float* __restrict__ Wout,
                const float* __restrict__ bout,
                float* __restrict__ out) {
    __shared__ float sacc[H_];
    const int b = blockIdx.x;
    const int o = threadIdx.x;
    for (int h = o; h < H_; h += O_) sacc[h] = g_acc[b * H_ + h];
    __syncthreads();
    float sum = bout[o];
#pragma unroll 8
    for (int h = 0; h < H_; h++)
        sum = fmaf(sacc[h], Wout[h * O_ + o], sum);
    out[b * O_ + o] = sum;
}

// ---------------------------------------------------------------------------
extern "C" void kernel_launch(void* const* d_in, const int* in_sizes, int n_in,
                              void* d_out, int out_size) {
    const float* x     = (const float*)d_in[0];
    const float* v0    = (const float*)d_in[1];
    const float* Wb    = (const float*)d_in[2];
    const float* tau_n = (const float*)d_in[3];
    const float* tau_m = (const float*)d_in[4];
    const float* Wout  = (const float*)d_in[5];
    const float* bout  = (const float*)d_in[6];
    float* out = (float*)d_out;
    (void)in_sizes; (void)n_in; (void)out_size;

    static bool attr_set = false;
    if (!attr_set) {
        cudaFuncSetAttribute(gemm_mma_kernel,
                             cudaFuncAttributeMaxDynamicSharedMemorySize,
                             SMEM_GEMM);
        attr_set = true;
    }

    split_x_kernel<<<(M_ * I_ / 4) / 256, 256>>>(x);   // launch 0
    split_w_kernel<<<(H_ * I_) / 256, 256>>>(Wb);      // launch 1
    probe_kernel<<<1, 32>>>();                          // launch 2 (ncu slot pad)

    dim3 ggrid(H_ / 128, M_ / 128);   // (8, 1024)
    gemm_mma_kernel<<<ggrid, 256, SMEM_GEMM>>>();      // launch 3 <- ncu capture

    recur_kernel<<<(B_ * H_) / 256, 256>>>(v0, tau_n, tau_m);
    out_kernel<<<B_, O_>>>(Wout, bout, out);
}